// round 1
// baseline (speedup 1.0000x reference)
#include <cuda_runtime.h>
#include <cstdint>

// BandSplit: per-band GroupNorm(1) + 1x1 Conv, folded into stats + GEMM + affine epilogue.
// x: [8, 2, 2049, 512, 2] f32, gamma/beta: [8196], W: [128, 8196], bias: [31, 128]
// out: [8, 128, 31, 512] f32

#define NBANDS 31
#define BATCH 8
#define T 512
#define OUTCH 128
#define FTOT 2049
#define TOTCH 8196
#define XBATCH (2 * 2049 * 512 * 2)  // 4196352 floats per sample

__constant__ int c_start[NBANDS] = {
    0, 25, 50, 75, 100, 125, 150, 175, 200, 225,
    250, 300, 350, 400, 450, 500, 550, 600, 650, 700, 750, 800,
    850, 950, 1050, 1150, 1250, 1350, 1450, 1550,
    1650};
__constant__ int c_width[NBANDS] = {
    25, 25, 25, 25, 25, 25, 25, 25, 25, 25,
    50, 50, 50, 50, 50, 50, 50, 50, 50, 50, 50, 50,
    100, 100, 100, 100, 100, 100, 100, 100,
    399};

// scratch (no allocs allowed)
__device__ int   g_offs[TOTCH];            // per global-channel base offset into x[b] (in floats)
__device__ float g_Swg[NBANDS * OUTCH];    // sum_c W[o,c]*gamma[c] per band
__device__ float g_Swb[NBANDS * OUTCH];    // sum_c W[o,c]*beta[c]  per band
__device__ float g_mu[BATCH * NBANDS];
__device__ float g_rstd[BATCH * NBANDS];

// ---------------------------------------------------------------------------
// K0: channel -> x offset table.  c = r*2w + ci*w + f  maps to x[b, ci, s+f, t, r]
// ---------------------------------------------------------------------------
__global__ void k_offs() {
    int gc = blockIdx.x * 256 + threadIdx.x;
    if (gc >= TOTCH) return;
    int i = 0;
    while (i < NBANDS - 1 && gc >= 4 * c_start[i + 1]) i++;
    int s = c_start[i], w = c_width[i];
    int c = gc - 4 * s;
    int r = c / (2 * w);
    int rem = c - r * 2 * w;
    int ci = rem / w;
    int f = rem - ci * w;
    g_offs[gc] = (ci * FTOT + s + f) * (T * 2) + r;
}

// ---------------------------------------------------------------------------
// K1: per-(band, out-channel) reductions of W*gamma and W*beta
// ---------------------------------------------------------------------------
__global__ void k_wsums(const float* __restrict__ W,
                        const float* __restrict__ gamma,
                        const float* __restrict__ beta) {
    int band = blockIdx.x;
    int o = blockIdx.y;
    int off = 4 * c_start[band];
    int ch = 4 * c_width[band];
    const float* Wr = W + (size_t)o * TOTCH + off;
    float sg = 0.f, sb = 0.f;
    for (int c = threadIdx.x; c < ch; c += 128) {
        float wv = Wr[c];
        sg += wv * gamma[off + c];
        sb += wv * beta[off + c];
    }
#pragma unroll
    for (int d = 16; d > 0; d >>= 1) {
        sg += __shfl_down_sync(0xffffffffu, sg, d);
        sb += __shfl_down_sync(0xffffffffu, sb, d);
    }
    __shared__ float s1[4], s2[4];
    int lane = threadIdx.x & 31, wid = threadIdx.x >> 5;
    if (lane == 0) { s1[wid] = sg; s2[wid] = sb; }
    __syncthreads();
    if (threadIdx.x == 0) {
        float tg = s1[0] + s1[1] + s1[2] + s1[3];
        float tb = s2[0] + s2[1] + s2[2] + s2[3];
        g_Swg[band * OUTCH + o] = tg;
        g_Swb[band * OUTCH + o] = tb;
    }
}

// ---------------------------------------------------------------------------
// K2: per-(batch, band) mean / rstd over the [4w, 512] slab
// ---------------------------------------------------------------------------
__global__ __launch_bounds__(512) void k_stats(const float* __restrict__ x) {
    int band = blockIdx.x;
    int b = blockIdx.y;
    int s = c_start[band], w = c_width[band];
    const float* base = x + (size_t)b * XBATCH;
    float sum = 0.f, sq = 0.f;
    int n4 = w * 256;  // float4 count per ci slab (w*1024 floats)
    for (int ci = 0; ci < 2; ci++) {
        const float4* p = (const float4*)(base + (size_t)(ci * FTOT + s) * (T * 2));
        for (int j = threadIdx.x; j < n4; j += 512) {
            float4 v = p[j];
            sum += v.x + v.y + v.z + v.w;
            sq += v.x * v.x + v.y * v.y + v.z * v.z + v.w * v.w;
        }
    }
#pragma unroll
    for (int d = 16; d > 0; d >>= 1) {
        sum += __shfl_down_sync(0xffffffffu, sum, d);
        sq += __shfl_down_sync(0xffffffffu, sq, d);
    }
    __shared__ float s1[16], s2[16];
    int lane = threadIdx.x & 31, wid = threadIdx.x >> 5;
    if (lane == 0) { s1[wid] = sum; s2[wid] = sq; }
    __syncthreads();
    if (threadIdx.x < 16) {
        sum = s1[threadIdx.x];
        sq = s2[threadIdx.x];
#pragma unroll
        for (int d = 8; d > 0; d >>= 1) {
            sum += __shfl_down_sync(0xffffu, sum, d);
            sq += __shfl_down_sync(0xffffu, sq, d);
        }
        if (threadIdx.x == 0) {
            float N = (float)(4 * w * T);
            float mu = sum / N;
            float var = sq / N - mu * mu;
            g_mu[b * NBANDS + band] = mu;
            g_rstd[b * NBANDS + band] = rsqrtf(var + 1e-5f);
        }
    }
}

// ---------------------------------------------------------------------------
// K3: per-band GEMM  [128 x ch] * [ch x 64] tiles, folded affine epilogue.
// Block = 256 threads; tile M=128 (full out-ch), N=64 t, K=32.
// ---------------------------------------------------------------------------
__global__ __launch_bounds__(256) void k_gemm(const float* __restrict__ x,
                                              const float* __restrict__ W,
                                              const float* __restrict__ gamma,
                                              const float* __restrict__ bias,
                                              float* __restrict__ out) {
    const int band = blockIdx.z;
    const int b = blockIdx.y;
    const int t0 = blockIdx.x * 64;
    const int s = c_start[band], w = c_width[band];
    const int off = 4 * s;
    const int ch = 4 * w;

    const float* xb = x + (size_t)b * XBATCH;
    const int* offs = g_offs + off;

    __shared__ float As[32][129];
    __shared__ float Bs[32][65];

    const int tid = threadIdx.x;
    const int tx = tid & 15;   // N dir: 16 * 4 = 64
    const int ty = tid >> 4;   // M dir: 16 * 8 = 128

    float acc[8][4];
#pragma unroll
    for (int m = 0; m < 8; m++)
#pragma unroll
        for (int j = 0; j < 4; j++) acc[m][j] = 0.f;

    for (int k0 = 0; k0 < ch; k0 += 32) {
        // A tile: W*gamma, 128 x 32
#pragma unroll
        for (int i = 0; i < 16; i++) {
            int e = i * 256 + tid;
            int k = e & 31, m = e >> 5;
            int c = k0 + k;
            As[k][m] = (c < ch) ? W[(size_t)m * TOTCH + off + c] * gamma[off + c] : 0.f;
        }
        // B tile: gathered x, 32 x 64
#pragma unroll
        for (int i = 0; i < 8; i++) {
            int e = i * 256 + tid;
            int t = e & 63, k = e >> 6;
            int c = k0 + k;
            Bs[k][t] = (c < ch) ? xb[offs[c] + (t0 + t) * 2] : 0.f;
        }
        __syncthreads();
#pragma unroll
        for (int k = 0; k < 32; k++) {
            float a[8], bb[4];
#pragma unroll
            for (int m = 0; m < 8; m++) a[m] = As[k][ty * 8 + m];
#pragma unroll
            for (int j = 0; j < 4; j++) bb[j] = Bs[k][tx * 4 + j];
#pragma unroll
            for (int m = 0; m < 8; m++)
#pragma unroll
                for (int j = 0; j < 4; j++) acc[m][j] += a[m] * bb[j];
        }
        __syncthreads();
    }

    const float mu = g_mu[b * NBANDS + band];
    const float rstd = g_rstd[b * NBANDS + band];
#pragma unroll
    for (int m = 0; m < 8; m++) {
        int o = ty * 8 + m;
        float add = g_Swb[band * OUTCH + o] - rstd * mu * g_Swg[band * OUTCH + o] +
                    bias[band * OUTCH + o];
        float4 v;
        v.x = rstd * acc[m][0] + add;
        v.y = rstd * acc[m][1] + add;
        v.z = rstd * acc[m][2] + add;
        v.w = rstd * acc[m][3] + add;
        *(float4*)(out + (((size_t)(b * OUTCH + o) * NBANDS + band) * T + t0 + tx * 4)) = v;
    }
}

extern "C" void kernel_launch(void* const* d_in, const int* in_sizes, int n_in,
                              void* d_out, int out_size) {
    (void)in_sizes; (void)n_in; (void)out_size;
    const float* x = (const float*)d_in[0];
    const float* gamma = (const float*)d_in[1];
    const float* beta = (const float*)d_in[2];
    const float* W = (const float*)d_in[3];
    const float* bias = (const float*)d_in[4];
    float* out = (float*)d_out;

    k_offs<<<(TOTCH + 255) / 256, 256>>>();
    k_wsums<<<dim3(NBANDS, OUTCH), 128>>>(W, gamma, beta);
    k_stats<<<dim3(NBANDS, BATCH), 512>>>(x);
    k_gemm<<<dim3(T / 64, BATCH, NBANDS), 256>>>(x, W, gamma, bias, out);
}

// round 2
// speedup vs baseline: 2.3152x; 2.3152x over previous
#include <cuda_runtime.h>
#include <cstdint>

// BandSplit: per-band GroupNorm(1) + 1x1 Conv, folded into stats + tf32-MMA GEMM + affine epilogue.
// x: [8, 2, 2049, 512, 2] f32, gamma/beta: [8196], W: [128, 8196], bias: [31, 128]
// out: [8, 128, 31, 512] f32

#define NBANDS 31
#define BATCH 8
#define T 512
#define OUTCH 128
#define FTOT 2049
#define TOTCH 8196
#define XBATCH (2 * 2049 * 512 * 2)

__constant__ int c_start[NBANDS] = {
    0, 25, 50, 75, 100, 125, 150, 175, 200, 225,
    250, 300, 350, 400, 450, 500, 550, 600, 650, 700, 750, 800,
    850, 950, 1050, 1150, 1250, 1350, 1450, 1550,
    1650};
__constant__ int c_width[NBANDS] = {
    25, 25, 25, 25, 25, 25, 25, 25, 25, 25,
    50, 50, 50, 50, 50, 50, 50, 50, 50, 50, 50, 50,
    100, 100, 100, 100, 100, 100, 100, 100,
    399};

// scratch (no allocs allowed)
__device__ int   g_wcol[TOTCH];        // permuted q -> original W column
__device__ int   g_xoff2[TOTCH / 2];   // per even-q: float2 base offset into x[b]
__device__ float g_Wg[OUTCH * TOTCH];  // W*gamma, K-permuted, [o][q]
__device__ float g_Swg[NBANDS * OUTCH];
__device__ float g_Swb[NBANDS * OUTCH];
__device__ float g_mu[BATCH * NBANDS];
__device__ float g_rstd[BATCH * NBANDS];

__device__ __forceinline__ float to_tf32(float f) {
    uint32_t u;
    asm("cvt.rna.tf32.f32 %0, %1;" : "=r"(u) : "f"(f));
    return __uint_as_float(u);
}

// ---------------------------------------------------------------------------
// K0: permutation tables. Permuted within-band index q = (ci*w + f)*2 + r.
// Original channel c = r*2w + ci*w + f; x element = x[b, ci, s+f, t, r].
// ---------------------------------------------------------------------------
__global__ void k_offs() {
    int gq = blockIdx.x * 256 + threadIdx.x;
    if (gq >= TOTCH) return;
    int i = 0;
    while (i < NBANDS - 1 && gq >= 4 * c_start[i + 1]) i++;
    int s = c_start[i], w = c_width[i];
    int qb = gq - 4 * s;
    int r = qb & 1, p = qb >> 1;
    int ci = p / w, f = p - ci * w;
    g_wcol[gq] = 4 * s + r * 2 * w + ci * w + f;
    if (r == 0) g_xoff2[gq >> 1] = (ci * FTOT + s + f) * (T * 2);
}

// K0b: pre-permuted, gamma-scaled A matrix
__global__ void k_prep(const float* __restrict__ W, const float* __restrict__ gamma) {
    int q = blockIdx.x * 256 + threadIdx.x;
    if (q >= TOTCH) return;
    int o = blockIdx.y;
    int c = g_wcol[q];
    g_Wg[(size_t)o * TOTCH + q] = W[(size_t)o * TOTCH + c] * gamma[c];
}

// ---------------------------------------------------------------------------
// K1: per-(band, out-channel) reductions of W*gamma and W*beta
// ---------------------------------------------------------------------------
__global__ void k_wsums(const float* __restrict__ W,
                        const float* __restrict__ gamma,
                        const float* __restrict__ beta) {
    int band = blockIdx.x;
    int o = blockIdx.y;
    int off = 4 * c_start[band];
    int ch = 4 * c_width[band];
    const float* Wr = W + (size_t)o * TOTCH + off;
    float sg = 0.f, sb = 0.f;
    for (int c = threadIdx.x; c < ch; c += 128) {
        float wv = Wr[c];
        sg += wv * gamma[off + c];
        sb += wv * beta[off + c];
    }
#pragma unroll
    for (int d = 16; d > 0; d >>= 1) {
        sg += __shfl_down_sync(0xffffffffu, sg, d);
        sb += __shfl_down_sync(0xffffffffu, sb, d);
    }
    __shared__ float s1[4], s2[4];
    int lane = threadIdx.x & 31, wid = threadIdx.x >> 5;
    if (lane == 0) { s1[wid] = sg; s2[wid] = sb; }
    __syncthreads();
    if (threadIdx.x == 0) {
        g_Swg[band * OUTCH + o] = s1[0] + s1[1] + s1[2] + s1[3];
        g_Swb[band * OUTCH + o] = s2[0] + s2[1] + s2[2] + s2[3];
    }
}

// ---------------------------------------------------------------------------
// K2: per-(batch, band) mean / rstd over the [4w, 512] slab (exact fp32)
// ---------------------------------------------------------------------------
__global__ __launch_bounds__(512) void k_stats(const float* __restrict__ x) {
    int band = blockIdx.x;
    int b = blockIdx.y;
    int s = c_start[band], w = c_width[band];
    const float* base = x + (size_t)b * XBATCH;
    float sum = 0.f, sq = 0.f;
    int n4 = w * 256;
    for (int ci = 0; ci < 2; ci++) {
        const float4* p = (const float4*)(base + (size_t)(ci * FTOT + s) * (T * 2));
        for (int j = threadIdx.x; j < n4; j += 512) {
            float4 v = p[j];
            sum += v.x + v.y + v.z + v.w;
            sq += v.x * v.x + v.y * v.y + v.z * v.z + v.w * v.w;
        }
    }
#pragma unroll
    for (int d = 16; d > 0; d >>= 1) {
        sum += __shfl_down_sync(0xffffffffu, sum, d);
        sq += __shfl_down_sync(0xffffffffu, sq, d);
    }
    __shared__ float s1[16], s2[16];
    int lane = threadIdx.x & 31, wid = threadIdx.x >> 5;
    if (lane == 0) { s1[wid] = sum; s2[wid] = sq; }
    __syncthreads();
    if (threadIdx.x < 16) {
        sum = s1[threadIdx.x];
        sq = s2[threadIdx.x];
#pragma unroll
        for (int d = 8; d > 0; d >>= 1) {
            sum += __shfl_down_sync(0xffffu, sum, d);
            sq += __shfl_down_sync(0xffffu, sq, d);
        }
        if (threadIdx.x == 0) {
            float N = (float)(4 * w * T);
            float mu = sum / N;
            float var = sq / N - mu * mu;
            g_mu[b * NBANDS + band] = mu;
            g_rstd[b * NBANDS + band] = rsqrtf(var + 1e-5f);
        }
    }
}

// ---------------------------------------------------------------------------
// K3: per-band GEMM via tf32 mma.sync. Block tile M=128 N=64 K=16, 8 warps
// (4x2), warp tile 32x32 = 2x4 m16n8k8 fragments per 8-k step.
// ---------------------------------------------------------------------------
__global__ __launch_bounds__(256) void k_gemm(const float* __restrict__ x,
                                              const float* __restrict__ bias,
                                              float* __restrict__ out) {
    const int band = blockIdx.z;
    const int b = blockIdx.y;
    const int t0 = blockIdx.x * 64;
    const int s = c_start[band], w = c_width[band];
    const int off = 4 * s;
    const int ch = 4 * w;
    const float* xb = x + (size_t)b * XBATCH;

    __shared__ float As[128][20];  // [m][k], stride 20 -> conflict-free frags
    __shared__ float Bs[16][68];   // [k][t], stride 68 -> conflict-free frags

    const int tid = threadIdx.x;
    const int lane = tid & 31, warp = tid >> 5;
    const int g = lane >> 2, tg = lane & 3;
    const int mw = (warp >> 1) * 32, nw = (warp & 1) * 32;

    // global-load mappings
    const int am0 = tid >> 2;          // A row (and +64)
    const int ak4 = (tid & 3) * 4;     // A k base (float4)
    const int bt = tid & 63;           // B t
    const int bk = tid >> 6;           // B k-pair (and +4)

    float d[2][4][4];
#pragma unroll
    for (int mt = 0; mt < 2; mt++)
#pragma unroll
        for (int nt = 0; nt < 4; nt++)
#pragma unroll
            for (int j = 0; j < 4; j++) d[mt][nt][j] = 0.f;

    const int niter = (ch + 15) >> 4;

    auto loadA = [&](int k0, int j) -> float4 {
        int m = am0 + j * 64;
        int kb = k0 + ak4;
        const float* src = g_Wg + (size_t)m * TOTCH + off + kb;
        float4 v = {0.f, 0.f, 0.f, 0.f};
        if (kb + 4 <= ch) {
            v = *(const float4*)src;
        } else {
            if (kb + 0 < ch) v.x = src[0];
            if (kb + 1 < ch) v.y = src[1];
            if (kb + 2 < ch) v.z = src[2];
            if (kb + 3 < ch) v.w = src[3];
        }
        return v;
    };
    auto loadB = [&](int k0, int j) -> float2 {
        int kk = k0 + (bk + j * 4) * 2;
        float2 v = {0.f, 0.f};
        if (kk < ch) {
            int base = g_xoff2[(off + kk) >> 1];
            v = *(const float2*)(xb + base + (t0 + bt) * 2);
        }
        return v;
    };

    float4 aReg[2];
    float2 bReg[2];
    aReg[0] = loadA(0, 0); aReg[1] = loadA(0, 1);
    bReg[0] = loadB(0, 0); bReg[1] = loadB(0, 1);

    for (int it = 0; it < niter; it++) {
        __syncthreads();  // previous compute done before overwriting smem
#pragma unroll
        for (int j = 0; j < 2; j++) {
            float4 v = aReg[j];
            v.x = to_tf32(v.x); v.y = to_tf32(v.y);
            v.z = to_tf32(v.z); v.w = to_tf32(v.w);
            *(float4*)&As[am0 + j * 64][ak4] = v;
        }
#pragma unroll
        for (int j = 0; j < 2; j++) {
            int kp = bk + j * 4;
            Bs[kp * 2][bt] = to_tf32(bReg[j].x);
            Bs[kp * 2 + 1][bt] = to_tf32(bReg[j].y);
        }
        __syncthreads();

        if (it + 1 < niter) {
            int kn = (it + 1) * 16;
            aReg[0] = loadA(kn, 0); aReg[1] = loadA(kn, 1);
            bReg[0] = loadB(kn, 0); bReg[1] = loadB(kn, 1);
        }

#pragma unroll
        for (int kk = 0; kk < 16; kk += 8) {
            uint32_t a[2][4], bb[4][2];
#pragma unroll
            for (int mt = 0; mt < 2; mt++) {
                int rb = mw + mt * 16;
                a[mt][0] = __float_as_uint(As[rb + g][kk + tg]);
                a[mt][1] = __float_as_uint(As[rb + g + 8][kk + tg]);
                a[mt][2] = __float_as_uint(As[rb + g][kk + tg + 4]);
                a[mt][3] = __float_as_uint(As[rb + g + 8][kk + tg + 4]);
            }
#pragma unroll
            for (int nt = 0; nt < 4; nt++) {
                int cb = nw + nt * 8 + g;
                bb[nt][0] = __float_as_uint(Bs[kk + tg][cb]);
                bb[nt][1] = __float_as_uint(Bs[kk + tg + 4][cb]);
            }
#pragma unroll
            for (int mt = 0; mt < 2; mt++)
#pragma unroll
                for (int nt = 0; nt < 4; nt++)
                    asm volatile(
                        "mma.sync.aligned.m16n8k8.row.col.f32.tf32.tf32.f32 "
                        "{%0,%1,%2,%3}, {%4,%5,%6,%7}, {%8,%9}, {%0,%1,%2,%3};"
                        : "+f"(d[mt][nt][0]), "+f"(d[mt][nt][1]),
                          "+f"(d[mt][nt][2]), "+f"(d[mt][nt][3])
                        : "r"(a[mt][0]), "r"(a[mt][1]), "r"(a[mt][2]), "r"(a[mt][3]),
                          "r"(bb[nt][0]), "r"(bb[nt][1]));
        }
    }

    const float mu = g_mu[b * NBANDS + band];
    const float rstd = g_rstd[b * NBANDS + band];
#pragma unroll
    for (int mt = 0; mt < 2; mt++) {
        int o0 = mw + mt * 16 + g;
        int o1 = o0 + 8;
        float add0 = g_Swb[band * OUTCH + o0] - rstd * mu * g_Swg[band * OUTCH + o0] +
                     bias[band * OUTCH + o0];
        float add1 = g_Swb[band * OUTCH + o1] - rstd * mu * g_Swg[band * OUTCH + o1] +
                     bias[band * OUTCH + o1];
#pragma unroll
        for (int nt = 0; nt < 4; nt++) {
            int t = t0 + nw + nt * 8 + 2 * tg;
            float2 v0 = {rstd * d[mt][nt][0] + add0, rstd * d[mt][nt][1] + add0};
            float2 v1 = {rstd * d[mt][nt][2] + add1, rstd * d[mt][nt][3] + add1};
            *(float2*)(out + (((size_t)(b * OUTCH + o0) * NBANDS + band) * T + t)) = v0;
            *(float2*)(out + (((size_t)(b * OUTCH + o1) * NBANDS + band) * T + t)) = v1;
        }
    }
}

extern "C" void kernel_launch(void* const* d_in, const int* in_sizes, int n_in,
                              void* d_out, int out_size) {
    (void)in_sizes; (void)n_in; (void)out_size;
    const float* x = (const float*)d_in[0];
    const float* gamma = (const float*)d_in[1];
    const float* beta = (const float*)d_in[2];
    const float* W = (const float*)d_in[3];
    const float* bias = (const float*)d_in[4];
    float* out = (float*)d_out;

    k_offs<<<(TOTCH + 255) / 256, 256>>>();
    k_prep<<<dim3((TOTCH + 255) / 256, OUTCH), 256>>>(W, gamma);
    k_wsums<<<dim3(NBANDS, OUTCH), 128>>>(W, gamma, beta);
    k_stats<<<dim3(NBANDS, BATCH), 512>>>(x);
    k_gemm<<<dim3(T / 64, BATCH, NBANDS), 256>>>(x, bias, out);
}

// round 3
// speedup vs baseline: 3.2370x; 1.3982x over previous
#include <cuda_runtime.h>
#include <cstdint>

// BandSplit: per-band GroupNorm(1) + 1x1 Conv = stats + tf32-MMA GEMM + affine epilogue.
// x: [8, 2, 2049, 512, 2] f32, gamma/beta: [8196], W: [128, 8196], bias: [31, 128]
// out: [8, 128, 31, 512] f32

#define NBANDS 31
#define BATCH 8
#define T 512
#define OUTCH 128
#define FTOT 2049
#define TOTCH 8196
#define XBATCH (2 * 2049 * 512 * 2)

__constant__ int c_start[NBANDS] = {
    0, 25, 50, 75, 100, 125, 150, 175, 200, 225,
    250, 300, 350, 400, 450, 500, 550, 600, 650, 700, 750, 800,
    850, 950, 1050, 1150, 1250, 1350, 1450, 1550,
    1650};
__constant__ int c_width[NBANDS] = {
    25, 25, 25, 25, 25, 25, 25, 25, 25, 25,
    50, 50, 50, 50, 50, 50, 50, 50, 50, 50, 50, 50,
    100, 100, 100, 100, 100, 100, 100, 100,
    399};

// scratch (no allocs allowed)
__device__ int   g_wcol[TOTCH];        // permuted q -> original W column
__device__ int   g_xoff2[TOTCH / 2];   // per even-q: float2 base offset into x[b]
__device__ float g_Wg[OUTCH * TOTCH];  // W*gamma (tf32-rounded), K-permuted, [o][q]
__device__ float g_Swg[NBANDS * OUTCH];
__device__ float g_Swb[NBANDS * OUTCH];
__device__ float g_mu[BATCH * NBANDS];
__device__ float g_rstd[BATCH * NBANDS];
__device__ float g_fsum[BATCH * FTOT];
__device__ float g_fsq[BATCH * FTOT];

__device__ __forceinline__ float to_tf32(float f) {
    uint32_t u;
    asm("cvt.rna.tf32.f32 %0, %1;" : "=r"(u) : "f"(f));
    return __uint_as_float(u);
}

// ---------------------------------------------------------------------------
// K0: permutation tables. Permuted within-band index q = (ci*w + f)*2 + r.
// Original channel c = r*2w + ci*w + f; x element = x[b, ci, s+f, t, r].
// ---------------------------------------------------------------------------
__global__ void k_offs() {
    int gq = blockIdx.x * 256 + threadIdx.x;
    if (gq >= TOTCH) return;
    int i = 0;
    while (i < NBANDS - 1 && gq >= 4 * c_start[i + 1]) i++;
    int s = c_start[i], w = c_width[i];
    int qb = gq - 4 * s;
    int r = qb & 1, p = qb >> 1;
    int ci = p / w, f = p - ci * w;
    g_wcol[gq] = 4 * s + r * 2 * w + ci * w + f;
    if (r == 0) g_xoff2[gq >> 1] = (ci * FTOT + s + f) * (T * 2);
}

// K0b: pre-permuted, gamma-scaled, tf32-rounded A matrix
__global__ void k_prep(const float* __restrict__ W, const float* __restrict__ gamma) {
    int q = blockIdx.x * 256 + threadIdx.x;
    if (q >= TOTCH) return;
    int o = blockIdx.y;
    int c = g_wcol[q];
    g_Wg[(size_t)o * TOTCH + q] = to_tf32(W[(size_t)o * TOTCH + c] * gamma[c]);
}

// ---------------------------------------------------------------------------
// K1: per-(band, out-channel) reductions of W*gamma and W*beta (fp32-exact)
// ---------------------------------------------------------------------------
__global__ void k_wsums(const float* __restrict__ W,
                        const float* __restrict__ gamma,
                        const float* __restrict__ beta) {
    int band = blockIdx.x;
    int o = blockIdx.y;
    int off = 4 * c_start[band];
    int ch = 4 * c_width[band];
    const float* Wr = W + (size_t)o * TOTCH + off;
    float sg = 0.f, sb = 0.f;
    for (int c = threadIdx.x; c < ch; c += 128) {
        float wv = Wr[c];
        sg += wv * gamma[off + c];
        sb += wv * beta[off + c];
    }
#pragma unroll
    for (int d = 16; d > 0; d >>= 1) {
        sg += __shfl_down_sync(0xffffffffu, sg, d);
        sb += __shfl_down_sync(0xffffffffu, sb, d);
    }
    __shared__ float s1[4], s2[4];
    int lane = threadIdx.x & 31, wid = threadIdx.x >> 5;
    if (lane == 0) { s1[wid] = sg; s2[wid] = sb; }
    __syncthreads();
    if (threadIdx.x == 0) {
        g_Swg[band * OUTCH + o] = s1[0] + s1[1] + s1[2] + s1[3];
        g_Swb[band * OUTCH + o] = s2[0] + s2[1] + s2[2] + s2[3];
    }
}

// ---------------------------------------------------------------------------
// K2a: per-(b, f) sum/sumsq over [2 ch x 512 t x 2 reim] = 2048 floats.
// One warp per bin -> perfect load balance + coalescing.
// ---------------------------------------------------------------------------
__global__ __launch_bounds__(256) void k_fsums(const float* __restrict__ x) {
    int idx = blockIdx.x * 8 + (threadIdx.x >> 5);
    if (idx >= BATCH * FTOT) return;
    int b = idx / FTOT, f = idx - b * FTOT;
    int lane = threadIdx.x & 31;
    float sum = 0.f, sq = 0.f;
#pragma unroll
    for (int ci = 0; ci < 2; ci++) {
        const float4* p =
            (const float4*)(x + ((size_t)(b * 2 + ci) * FTOT + f) * (size_t)(T * 2));
#pragma unroll
        for (int i = 0; i < 8; i++) {
            float4 v = p[lane + i * 32];
            sum += v.x + v.y + v.z + v.w;
            sq += v.x * v.x + v.y * v.y + v.z * v.z + v.w * v.w;
        }
    }
#pragma unroll
    for (int d = 16; d > 0; d >>= 1) {
        sum += __shfl_down_sync(0xffffffffu, sum, d);
        sq += __shfl_down_sync(0xffffffffu, sq, d);
    }
    if (lane == 0) { g_fsum[idx] = sum; g_fsq[idx] = sq; }
}

// K2b: per-(band, batch) reduce bin sums -> mu, rstd
__global__ __launch_bounds__(128) void k_stats2() {
    int band = blockIdx.x, b = blockIdx.y;
    int s = c_start[band], w = c_width[band];
    float sum = 0.f, sq = 0.f;
    for (int j = threadIdx.x; j < w; j += 128) {
        int idx = b * FTOT + s + j;
        sum += g_fsum[idx];
        sq += g_fsq[idx];
    }
#pragma unroll
    for (int d = 16; d > 0; d >>= 1) {
        sum += __shfl_down_sync(0xffffffffu, sum, d);
        sq += __shfl_down_sync(0xffffffffu, sq, d);
    }
    __shared__ float s1[4], s2[4];
    int lane = threadIdx.x & 31, wid = threadIdx.x >> 5;
    if (lane == 0) { s1[wid] = sum; s2[wid] = sq; }
    __syncthreads();
    if (threadIdx.x == 0) {
        sum = s1[0] + s1[1] + s1[2] + s1[3];
        sq = s2[0] + s2[1] + s2[2] + s2[3];
        float N = (float)(4 * w * T);
        float mu = sum / N;
        float var = sq / N - mu * mu;
        g_mu[b * NBANDS + band] = mu;
        g_rstd[b * NBANDS + band] = rsqrtf(var + 1e-5f);
    }
}

// ---------------------------------------------------------------------------
// K3: per-band GEMM via tf32 mma.sync, double-buffered smem.
// Block tile M=128 N=64 K=16, 8 warps (4x2), warp tile 32x32.
// ---------------------------------------------------------------------------
__global__ __launch_bounds__(256) void k_gemm(const float* __restrict__ x,
                                              const float* __restrict__ bias,
                                              float* __restrict__ out) {
    const int band = blockIdx.z;
    const int b = blockIdx.y;
    const int t0 = blockIdx.x * 64;
    const int s = c_start[band], w = c_width[band];
    const int off = 4 * s;
    const int ch = 4 * w;
    const float* xb = x + (size_t)b * XBATCH;

    __shared__ float As[2][128][20];
    __shared__ float Bs[2][16][68];

    const int tid = threadIdx.x;
    const int lane = tid & 31, warp = tid >> 5;
    const int g = lane >> 2, tg = lane & 3;
    const int mw = (warp >> 1) * 32, nw = (warp & 1) * 32;

    const int am0 = tid >> 2;       // A row (and +64)
    const int ak4 = (tid & 3) * 4;  // A k base (float4)
    const int bt = tid & 63;        // B t
    const int bk = tid >> 6;        // B k-pair (and +4)

    float d[2][4][4];
#pragma unroll
    for (int mt = 0; mt < 2; mt++)
#pragma unroll
        for (int nt = 0; nt < 4; nt++)
#pragma unroll
            for (int j = 0; j < 4; j++) d[mt][nt][j] = 0.f;

    const int niter = (ch + 15) >> 4;

    auto loadA = [&](int k0, int j) -> float4 {
        int kb = k0 + ak4;
        if (kb >= ch) return make_float4(0.f, 0.f, 0.f, 0.f);
        return *(const float4*)(g_Wg + (size_t)(am0 + j * 64) * TOTCH + off + kb);
    };
    auto loadB = [&](int k0, int j) -> float2 {
        int kk = k0 + (bk + j * 4) * 2;
        if (kk >= ch) return make_float2(0.f, 0.f);
        int base = g_xoff2[(off + kk) >> 1];
        return *(const float2*)(xb + base + (t0 + bt) * 2);
    };
    auto storeTile = [&](int buf, float4 a0, float4 a1, float2 b0, float2 b1) {
        *(float4*)&As[buf][am0][ak4] = a0;
        *(float4*)&As[buf][am0 + 64][ak4] = a1;
        Bs[buf][bk * 2][bt] = to_tf32(b0.x);
        Bs[buf][bk * 2 + 1][bt] = to_tf32(b0.y);
        Bs[buf][(bk + 4) * 2][bt] = to_tf32(b1.x);
        Bs[buf][(bk + 4) * 2 + 1][bt] = to_tf32(b1.y);
    };

    {
        float4 a0 = loadA(0, 0), a1 = loadA(0, 1);
        float2 b0 = loadB(0, 0), b1 = loadB(0, 1);
        storeTile(0, a0, a1, b0, b1);
    }
    __syncthreads();

    for (int it = 0; it < niter; it++) {
        const int cur = it & 1;
        float4 a0, a1;
        float2 b0, b1;
        const bool more = (it + 1 < niter);
        if (more) {
            int kn = (it + 1) * 16;
            a0 = loadA(kn, 0); a1 = loadA(kn, 1);
            b0 = loadB(kn, 0); b1 = loadB(kn, 1);
        }

#pragma unroll
        for (int kk = 0; kk < 16; kk += 8) {
            uint32_t a[2][4], bb[4][2];
#pragma unroll
            for (int mt = 0; mt < 2; mt++) {
                int rb = mw + mt * 16;
                a[mt][0] = __float_as_uint(As[cur][rb + g][kk + tg]);
                a[mt][1] = __float_as_uint(As[cur][rb + g + 8][kk + tg]);
                a[mt][2] = __float_as_uint(As[cur][rb + g][kk + tg + 4]);
                a[mt][3] = __float_as_uint(As[cur][rb + g + 8][kk + tg + 4]);
            }
#pragma unroll
            for (int nt = 0; nt < 4; nt++) {
                int cb = nw + nt * 8 + g;
                bb[nt][0] = __float_as_uint(Bs[cur][kk + tg][cb]);
                bb[nt][1] = __float_as_uint(Bs[cur][kk + tg + 4][cb]);
            }
#pragma unroll
            for (int mt = 0; mt < 2; mt++)
#pragma unroll
                for (int nt = 0; nt < 4; nt++)
                    asm volatile(
                        "mma.sync.aligned.m16n8k8.row.col.f32.tf32.tf32.f32 "
                        "{%0,%1,%2,%3}, {%4,%5,%6,%7}, {%8,%9}, {%0,%1,%2,%3};"
                        : "+f"(d[mt][nt][0]), "+f"(d[mt][nt][1]),
                          "+f"(d[mt][nt][2]), "+f"(d[mt][nt][3])
                        : "r"(a[mt][0]), "r"(a[mt][1]), "r"(a[mt][2]), "r"(a[mt][3]),
                          "r"(bb[nt][0]), "r"(bb[nt][1]));
        }

        if (more) {
            storeTile(cur ^ 1, a0, a1, b0, b1);
            __syncthreads();
        }
    }

    const float mu = g_mu[b * NBANDS + band];
    const float rstd = g_rstd[b * NBANDS + band];
#pragma unroll
    for (int mt = 0; mt < 2; mt++) {
        int o0 = mw + mt * 16 + g;
        int o1 = o0 + 8;
        float add0 = g_Swb[band * OUTCH + o0] - rstd * mu * g_Swg[band * OUTCH + o0] +
                     bias[band * OUTCH + o0];
        float add1 = g_Swb[band * OUTCH + o1] - rstd * mu * g_Swg[band * OUTCH + o1] +
                     bias[band * OUTCH + o1];
#pragma unroll
        for (int nt = 0; nt < 4; nt++) {
            int t = t0 + nw + nt * 8 + 2 * tg;
            float2 v0 = {rstd * d[mt][nt][0] + add0, rstd * d[mt][nt][1] + add0};
            float2 v1 = {rstd * d[mt][nt][2] + add1, rstd * d[mt][nt][3] + add1};
            *(float2*)(out + (((size_t)(b * OUTCH + o0) * NBANDS + band) * T + t)) = v0;
            *(float2*)(out + (((size_t)(b * OUTCH + o1) * NBANDS + band) * T + t)) = v1;
        }
    }
}

extern "C" void kernel_launch(void* const* d_in, const int* in_sizes, int n_in,
                              void* d_out, int out_size) {
    (void)in_sizes; (void)n_in; (void)out_size;
    const float* x = (const float*)d_in[0];
    const float* gamma = (const float*)d_in[1];
    const float* beta = (const float*)d_in[2];
    const float* W = (const float*)d_in[3];
    const float* bias = (const float*)d_in[4];
    float* out = (float*)d_out;

    k_offs<<<(TOTCH + 255) / 256, 256>>>();
    k_prep<<<dim3((TOTCH + 255) / 256, OUTCH), 256>>>(W, gamma);
    k_wsums<<<dim3(NBANDS, OUTCH), 128>>>(W, gamma, beta);
    k_fsums<<<(BATCH * FTOT + 7) / 8, 256>>>(x);
    k_stats2<<<dim3(NBANDS, BATCH), 128>>>();
    k_gemm<<<dim3(T / 64, BATCH, NBANDS), 256>>>(x, bias, out);
}

// round 4
// speedup vs baseline: 5.3629x; 1.6568x over previous
#include <cuda_runtime.h>
#include <cstdint>

// BandSplit: per-band GroupNorm(1) + 1x1 Conv = stats + tf32-MMA GEMM + affine epilogue.
// x: [8, 2, 2049, 512, 2] f32, gamma/beta: [8196], W: [128, 8196], bias: [31, 128]
// out: [8, 128, 31, 512] f32

#define NBANDS 31
#define BATCH 8
#define T 512
#define OUTCH 128
#define FTOT 2049
#define TOTCH 8196
#define XBATCH (2 * 2049 * 512 * 2)

__constant__ int c_start[NBANDS] = {
    0, 25, 50, 75, 100, 125, 150, 175, 200, 225,
    250, 300, 350, 400, 450, 500, 550, 600, 650, 700, 750, 800,
    850, 950, 1050, 1150, 1250, 1350, 1450, 1550,
    1650};
__constant__ int c_width[NBANDS] = {
    25, 25, 25, 25, 25, 25, 25, 25, 25, 25,
    50, 50, 50, 50, 50, 50, 50, 50, 50, 50, 50, 50,
    100, 100, 100, 100, 100, 100, 100, 100,
    399};
// heavy-first execution order (band 30 first so its 100-iter blocks start in wave 1)
__constant__ int c_perm[NBANDS] = {
    30, 22, 23, 24, 25, 26, 27, 28, 29,
    10, 11, 12, 13, 14, 15, 16, 17, 18, 19, 20, 21,
    0, 1, 2, 3, 4, 5, 6, 7, 8, 9};

// scratch (no allocs allowed)
__device__ int   g_xoff2[TOTCH / 2];   // per even-q: float2 base offset into x[b]
__device__ float g_Wg[OUTCH * TOTCH];  // W*gamma (tf32-rounded), K-permuted, [o][q]
__device__ float g_Swg[NBANDS * OUTCH];
__device__ float g_Swb[NBANDS * OUTCH];
__device__ float g_mu[BATCH * NBANDS];
__device__ float g_rstd[BATCH * NBANDS];
__device__ float g_fsum[BATCH * FTOT];
__device__ float g_fsq[BATCH * FTOT];

__device__ __forceinline__ float to_tf32(float f) {
    uint32_t u;
    asm("cvt.rna.tf32.f32 %0, %1;" : "=r"(u) : "f"(f));
    return __uint_as_float(u);
}
__device__ __forceinline__ uint32_t smaddr(const void* p) {
    return (uint32_t)__cvta_generic_to_shared(p);
}
__device__ __forceinline__ void cp16(uint32_t dst, const void* src, bool pred) {
    int sz = pred ? 16 : 0;
    asm volatile("cp.async.cg.shared.global [%0], [%1], 16, %2;\n" ::"r"(dst), "l"(src),
                 "r"(sz));
}
__device__ __forceinline__ void cp8(uint32_t dst, const void* src, bool pred) {
    int sz = pred ? 8 : 0;
    asm volatile("cp.async.ca.shared.global [%0], [%1], 8, %2;\n" ::"r"(dst), "l"(src),
                 "r"(sz));
}
__device__ __forceinline__ void cp_commit() {
    asm volatile("cp.async.commit_group;\n" ::);
}
__device__ __forceinline__ void cp_wait1() {
    asm volatile("cp.async.wait_group 1;\n" ::);
}

// ---------------------------------------------------------------------------
// K0: x offset table. Permuted within-band index q = (ci*w + f)*2 + r maps to
// original channel c = r*2w + ci*w + f; x element = x[b, ci, s+f, t, r].
// ---------------------------------------------------------------------------
__global__ void k_offs() {
    int gq = blockIdx.x * 256 + threadIdx.x;
    if (gq >= TOTCH || (gq & 1)) return;
    int i = 0;
    while (i < NBANDS - 1 && gq >= 4 * c_start[i + 1]) i++;
    int s = c_start[i], w = c_width[i];
    int p = (gq - 4 * s) >> 1;
    int ci = p / w, f = p - ci * w;
    g_xoff2[gq >> 1] = (ci * FTOT + s + f) * (T * 2);
}

// K0b: permuted, gamma-scaled, tf32-rounded A matrix. Coalesced both sides:
// one block per (band, o); threads stride the w frequencies, write float2 (r pair).
__global__ void k_prep(const float* __restrict__ W, const float* __restrict__ gamma) {
    int band = blockIdx.x;
    int o = blockIdx.y;
    int s4 = 4 * c_start[band], w = c_width[band];
    const float* Wr = W + (size_t)o * TOTCH + s4;
    const float* gr = gamma + s4;
    float* dst = g_Wg + (size_t)o * TOTCH + s4;
    for (int j = threadIdx.x; j < 2 * w; j += 256) {
        int ci = (j >= w) ? 1 : 0;
        int f = j - ci * w;
        int c0 = ci * w + f;            // r=0 channel (within band)
        int c1 = 2 * w + ci * w + f;    // r=1 channel
        float2 v;
        v.x = to_tf32(Wr[c0] * gr[c0]);
        v.y = to_tf32(Wr[c1] * gr[c1]);
        *(float2*)(dst + 2 * j) = v;    // q = 2*(ci*w+f) + r
    }
}

// ---------------------------------------------------------------------------
// K1: per-(band, out-channel) reductions of W*gamma and W*beta (fp32-exact)
// ---------------------------------------------------------------------------
__global__ void k_wsums(const float* __restrict__ W,
                        const float* __restrict__ gamma,
                        const float* __restrict__ beta) {
    int band = blockIdx.x;
    int o = blockIdx.y;
    int off = 4 * c_start[band];
    int ch = 4 * c_width[band];
    const float* Wr = W + (size_t)o * TOTCH + off;
    float sg = 0.f, sb = 0.f;
    for (int c = threadIdx.x; c < ch; c += 128) {
        float wv = Wr[c];
        sg += wv * gamma[off + c];
        sb += wv * beta[off + c];
    }
#pragma unroll
    for (int d = 16; d > 0; d >>= 1) {
        sg += __shfl_down_sync(0xffffffffu, sg, d);
        sb += __shfl_down_sync(0xffffffffu, sb, d);
    }
    __shared__ float s1[4], s2[4];
    int lane = threadIdx.x & 31, wid = threadIdx.x >> 5;
    if (lane == 0) { s1[wid] = sg; s2[wid] = sb; }
    __syncthreads();
    if (threadIdx.x == 0) {
        g_Swg[band * OUTCH + o] = s1[0] + s1[1] + s1[2] + s1[3];
        g_Swb[band * OUTCH + o] = s2[0] + s2[1] + s2[2] + s2[3];
    }
}

// ---------------------------------------------------------------------------
// K2a: per-(b, f) sum/sumsq over 2048 contiguous floats. One warp per bin.
// ---------------------------------------------------------------------------
__global__ __launch_bounds__(256) void k_fsums(const float* __restrict__ x) {
    int idx = blockIdx.x * 8 + (threadIdx.x >> 5);
    if (idx >= BATCH * FTOT) return;
    int b = idx / FTOT, f = idx - b * FTOT;
    int lane = threadIdx.x & 31;
    float sum = 0.f, sq = 0.f;
#pragma unroll
    for (int ci = 0; ci < 2; ci++) {
        const float4* p =
            (const float4*)(x + ((size_t)(b * 2 + ci) * FTOT + f) * (size_t)(T * 2));
#pragma unroll
        for (int i = 0; i < 8; i++) {
            float4 v = p[lane + i * 32];
            sum += v.x + v.y + v.z + v.w;
            sq += v.x * v.x + v.y * v.y + v.z * v.z + v.w * v.w;
        }
    }
#pragma unroll
    for (int d = 16; d > 0; d >>= 1) {
        sum += __shfl_down_sync(0xffffffffu, sum, d);
        sq += __shfl_down_sync(0xffffffffu, sq, d);
    }
    if (lane == 0) { g_fsum[idx] = sum; g_fsq[idx] = sq; }
}

// K2b: per-(band, batch) reduce bin sums -> mu, rstd
__global__ __launch_bounds__(128) void k_stats2() {
    int band = blockIdx.x, b = blockIdx.y;
    int s = c_start[band], w = c_width[band];
    float sum = 0.f, sq = 0.f;
    for (int j = threadIdx.x; j < w; j += 128) {
        int idx = b * FTOT + s + j;
        sum += g_fsum[idx];
        sq += g_fsq[idx];
    }
#pragma unroll
    for (int d = 16; d > 0; d >>= 1) {
        sum += __shfl_down_sync(0xffffffffu, sum, d);
        sq += __shfl_down_sync(0xffffffffu, sq, d);
    }
    __shared__ float s1[4], s2[4];
    int lane = threadIdx.x & 31, wid = threadIdx.x >> 5;
    if (lane == 0) { s1[wid] = sum; s2[wid] = sq; }
    __syncthreads();
    if (threadIdx.x == 0) {
        sum = s1[0] + s1[1] + s1[2] + s1[3];
        sq = s2[0] + s2[1] + s2[2] + s2[3];
        float N = (float)(4 * w * T);
        float mu = sum / N;
        float var = sq / N - mu * mu;
        g_mu[b * NBANDS + band] = mu;
        g_rstd[b * NBANDS + band] = rsqrtf(var + 1e-5f);
    }
}

// ---------------------------------------------------------------------------
// K3: per-band GEMM via tf32 mma.sync; 3-stage cp.async pipeline.
// Block tile M=128 N=64 K=16, 8 warps (4x2), warp tile 32x32.
// B enters raw f32; tensor core truncates to tf32 in HW.
// ---------------------------------------------------------------------------
__global__ __launch_bounds__(256) void k_gemm(const float* __restrict__ x,
                                              const float* __restrict__ bias,
                                              float* __restrict__ out) {
    const int band = c_perm[blockIdx.z];
    const int b = blockIdx.y;
    const int t0 = blockIdx.x * 64;
    const int s = c_start[band], w = c_width[band];
    const int off = 4 * s;
    const int ch = 4 * w;
    const float* xb = x + (size_t)b * XBATCH;

    __shared__ float As[3][128][20];     // [m][k], stride 20: conflict-free frags
    __shared__ float Bs[3][8][72][2];    // [k-pair][t][r-parity]: conflict-free frags

    const int tid = threadIdx.x;
    const int lane = tid & 31, warp = tid >> 5;
    const int g = lane >> 2, tg = lane & 3;
    const int mw = (warp >> 1) * 32, nw = (warp & 1) * 32;

    const int am0 = tid >> 2;       // A row (and +64)
    const int ak4 = (tid & 3) * 4;  // A k base (float4)
    const int bt = tid & 63;        // B t
    const int bp0 = tid >> 6;       // B k-pair (and +4)

    const int niter = (ch + 15) >> 4;

    auto issue = [&](int st, int k0) {
#pragma unroll
        for (int j = 0; j < 2; j++) {
            int kb = k0 + ak4;
            bool p = kb < ch;
            const float* src =
                g_Wg + (size_t)(am0 + j * 64) * TOTCH + off + (p ? kb : 0);
            cp16(smaddr(&As[st][am0 + j * 64][ak4]), src, p);
        }
#pragma unroll
        for (int j = 0; j < 2; j++) {
            int p = bp0 + j * 4;
            int kk = k0 + 2 * p;
            bool pr = kk < ch;
            int pi = (off + (pr ? kk : 0)) >> 1;
            const float* src = xb + g_xoff2[pi] + (t0 + bt) * 2;
            cp8(smaddr(&Bs[st][p][bt][0]), src, pr);
        }
    };

    float d[2][4][4];
#pragma unroll
    for (int mt = 0; mt < 2; mt++)
#pragma unroll
        for (int nt = 0; nt < 4; nt++)
#pragma unroll
            for (int j = 0; j < 4; j++) d[mt][nt][j] = 0.f;

    issue(0, 0);
    cp_commit();
    issue(1, 16);
    cp_commit();

    for (int it = 0; it < niter; it++) {
        const int cur = it % 3;
        cp_wait1();
        __syncthreads();
        {
            int nst = it + 2;
            if (nst < niter) issue(nst % 3, nst * 16);
            cp_commit();  // always commit (possibly empty) to keep group accounting
        }

#pragma unroll
        for (int kk = 0; kk < 16; kk += 8) {
            uint32_t a[2][4], bb[4][2];
#pragma unroll
            for (int mt = 0; mt < 2; mt++) {
                int rb = mw + mt * 16;
                a[mt][0] = __float_as_uint(As[cur][rb + g][kk + tg]);
                a[mt][1] = __float_as_uint(As[cur][rb + g + 8][kk + tg]);
                a[mt][2] = __float_as_uint(As[cur][rb + g][kk + tg + 4]);
                a[mt][3] = __float_as_uint(As[cur][rb + g + 8][kk + tg + 4]);
            }
            const int p0 = (kk + tg) >> 1, par = tg & 1;
#pragma unroll
            for (int nt = 0; nt < 4; nt++) {
                int cb = nw + nt * 8 + g;
                bb[nt][0] = __float_as_uint(Bs[cur][p0][cb][par]);
                bb[nt][1] = __float_as_uint(Bs[cur][p0 + 2][cb][par]);
            }
#pragma unroll
            for (int mt = 0; mt < 2; mt++)
#pragma unroll
                for (int nt = 0; nt < 4; nt++)
                    asm volatile(
                        "mma.sync.aligned.m16n8k8.row.col.f32.tf32.tf32.f32 "
                        "{%0,%1,%2,%3}, {%4,%5,%6,%7}, {%8,%9}, {%0,%1,%2,%3};"
                        : "+f"(d[mt][nt][0]), "+f"(d[mt][nt][1]),
                          "+f"(d[mt][nt][2]), "+f"(d[mt][nt][3])
                        : "r"(a[mt][0]), "r"(a[mt][1]), "r"(a[mt][2]), "r"(a[mt][3]),
                          "r"(bb[nt][0]), "r"(bb[nt][1]));
        }
    }

    const float mu = g_mu[b * NBANDS + band];
    const float rstd = g_rstd[b * NBANDS + band];
#pragma unroll
    for (int mt = 0; mt < 2; mt++) {
        int o0 = mw + mt * 16 + g;
        int o1 = o0 + 8;
        float add0 = g_Swb[band * OUTCH + o0] - rstd * mu * g_Swg[band * OUTCH + o0] +
                     bias[band * OUTCH + o0];
        float add1 = g_Swb[band * OUTCH + o1] - rstd * mu * g_Swg[band * OUTCH + o1] +
                     bias[band * OUTCH + o1];
#pragma unroll
        for (int nt = 0; nt < 4; nt++) {
            int t = t0 + nw + nt * 8 + 2 * tg;
            float2 v0 = {rstd * d[mt][nt][0] + add0, rstd * d[mt][nt][1] + add0};
            float2 v1 = {rstd * d[mt][nt][2] + add1, rstd * d[mt][nt][3] + add1};
            *(float2*)(out + (((size_t)(b * OUTCH + o0) * NBANDS + band) * T + t)) = v0;
            *(float2*)(out + (((size_t)(b * OUTCH + o1) * NBANDS + band) * T + t)) = v1;
        }
    }
}

extern "C" void kernel_launch(void* const* d_in, const int* in_sizes, int n_in,
                              void* d_out, int out_size) {
    (void)in_sizes; (void)n_in; (void)out_size;
    const float* x = (const float*)d_in[0];
    const float* gamma = (const float*)d_in[1];
    const float* beta = (const float*)d_in[2];
    const float* W = (const float*)d_in[3];
    const float* bias = (const float*)d_in[4];
    float* out = (float*)d_out;

    k_offs<<<(TOTCH + 255) / 256, 256>>>();
    k_prep<<<dim3(NBANDS, OUTCH), 256>>>(W, gamma);
    k_wsums<<<dim3(NBANDS, OUTCH), 128>>>(W, gamma, beta);
    k_fsums<<<(BATCH * FTOT + 7) / 8, 256>>>(x);
    k_stats2<<<dim3(NBANDS, BATCH), 128>>>();
    k_gemm<<<dim3(T / 64, BATCH, NBANDS), 256>>>(x, bias, out);
}

// round 5
// speedup vs baseline: 5.4346x; 1.0134x over previous
#include <cuda_runtime.h>
#include <cstdint>

// BandSplit: per-band GroupNorm(1) + 1x1 Conv = stats + tf32-MMA GEMM + affine epilogue.
// x: [8, 2, 2049, 512, 2] f32, gamma/beta: [8196], W: [128, 8196], bias: [31, 128]
// out: [8, 128, 31, 512] f32

#define NBANDS 31
#define BATCH 8
#define T 512
#define OUTCH 128
#define FTOT 2049
#define TOTCH 8196
#define XBATCH (2 * 2049 * 512 * 2)

__constant__ int c_start[NBANDS] = {
    0, 25, 50, 75, 100, 125, 150, 175, 200, 225,
    250, 300, 350, 400, 450, 500, 550, 600, 650, 700, 750, 800,
    850, 950, 1050, 1150, 1250, 1350, 1450, 1550,
    1650};
__constant__ int c_width[NBANDS] = {
    25, 25, 25, 25, 25, 25, 25, 25, 25, 25,
    50, 50, 50, 50, 50, 50, 50, 50, 50, 50, 50, 50,
    100, 100, 100, 100, 100, 100, 100, 100,
    399};
// heavy-first execution order (band 30 first so its 100-iter blocks start in wave 1)
__constant__ int c_perm[NBANDS] = {
    30, 22, 23, 24, 25, 26, 27, 28, 29,
    10, 11, 12, 13, 14, 15, 16, 17, 18, 19, 20, 21,
    0, 1, 2, 3, 4, 5, 6, 7, 8, 9};

// scratch (no allocs allowed)
__device__ int   g_xoff2[TOTCH / 2];   // per even-q: float2 base offset into x[b]
__device__ float g_Wg[OUTCH * TOTCH];  // W*gamma (tf32-rounded), K-permuted, [o][q]
__device__ float g_Swg[NBANDS * OUTCH];
__device__ float g_Swb[NBANDS * OUTCH];
__device__ float g_mu[BATCH * NBANDS];
__device__ float g_rstd[BATCH * NBANDS];
__device__ float g_fsum[BATCH * FTOT];
__device__ float g_fsq[BATCH * FTOT];

__device__ __forceinline__ float to_tf32(float f) {
    uint32_t u;
    asm("cvt.rna.tf32.f32 %0, %1;" : "=r"(u) : "f"(f));
    return __uint_as_float(u);
}
__device__ __forceinline__ uint32_t smaddr(const void* p) {
    return (uint32_t)__cvta_generic_to_shared(p);
}
__device__ __forceinline__ void cp16(uint32_t dst, const void* src, bool pred) {
    int sz = pred ? 16 : 0;
    asm volatile("cp.async.cg.shared.global [%0], [%1], 16, %2;\n" ::"r"(dst), "l"(src),
                 "r"(sz));
}
__device__ __forceinline__ void cp8(uint32_t dst, const void* src, bool pred) {
    int sz = pred ? 8 : 0;
    asm volatile("cp.async.ca.shared.global [%0], [%1], 8, %2;\n" ::"r"(dst), "l"(src),
                 "r"(sz));
}
__device__ __forceinline__ void cp_commit() {
    asm volatile("cp.async.commit_group;\n" ::);
}
__device__ __forceinline__ void cp_wait1() {
    asm volatile("cp.async.wait_group 1;\n" ::);
}

// ---------------------------------------------------------------------------
// K0: x offset table. Permuted within-band index q = (ci*w + f)*2 + r maps to
// original channel c = r*2w + ci*w + f; x element = x[b, ci, s+f, t, r].
// ---------------------------------------------------------------------------
__global__ void k_offs() {
    int gq = blockIdx.x * 256 + threadIdx.x;
    if (gq >= TOTCH || (gq & 1)) return;
    int i = 0;
    while (i < NBANDS - 1 && gq >= 4 * c_start[i + 1]) i++;
    int s = c_start[i], w = c_width[i];
    int p = (gq - 4 * s) >> 1;
    int ci = p / w, f = p - ci * w;
    g_xoff2[gq >> 1] = (ci * FTOT + s + f) * (T * 2);
}

// K0b: permuted, gamma-scaled, tf32-rounded A matrix. Coalesced both sides:
// one block per (band, o); threads stride the w frequencies, write float2 (r pair).
__global__ void k_prep(const float* __restrict__ W, const float* __restrict__ gamma) {
    int band = blockIdx.x;
    int o = blockIdx.y;
    int s4 = 4 * c_start[band], w = c_width[band];
    const float* Wr = W + (size_t)o * TOTCH + s4;
    const float* gr = gamma + s4;
    float* dst = g_Wg + (size_t)o * TOTCH + s4;
    for (int j = threadIdx.x; j < 2 * w; j += 256) {
        int ci = (j >= w) ? 1 : 0;
        int f = j - ci * w;
        int c0 = ci * w + f;            // r=0 channel (within band)
        int c1 = 2 * w + ci * w + f;    // r=1 channel
        float2 v;
        v.x = to_tf32(Wr[c0] * gr[c0]);
        v.y = to_tf32(Wr[c1] * gr[c1]);
        *(float2*)(dst + 2 * j) = v;    // q = 2*(ci*w+f) + r
    }
}

// ---------------------------------------------------------------------------
// K1: per-(band, out-channel) reductions of W*gamma and W*beta (fp32-exact)
// ---------------------------------------------------------------------------
__global__ void k_wsums(const float* __restrict__ W,
                        const float* __restrict__ gamma,
                        const float* __restrict__ beta) {
    int band = blockIdx.x;
    int o = blockIdx.y;
    int off = 4 * c_start[band];
    int ch = 4 * c_width[band];
    const float* Wr = W + (size_t)o * TOTCH + off;
    float sg = 0.f, sb = 0.f;
    for (int c = threadIdx.x; c < ch; c += 128) {
        float wv = Wr[c];
        sg += wv * gamma[off + c];
        sb += wv * beta[off + c];
    }
#pragma unroll
    for (int d = 16; d > 0; d >>= 1) {
        sg += __shfl_down_sync(0xffffffffu, sg, d);
        sb += __shfl_down_sync(0xffffffffu, sb, d);
    }
    __shared__ float s1[4], s2[4];
    int lane = threadIdx.x & 31, wid = threadIdx.x >> 5;
    if (lane == 0) { s1[wid] = sg; s2[wid] = sb; }
    __syncthreads();
    if (threadIdx.x == 0) {
        g_Swg[band * OUTCH + o] = s1[0] + s1[1] + s1[2] + s1[3];
        g_Swb[band * OUTCH + o] = s2[0] + s2[1] + s2[2] + s2[3];
    }
}

// ---------------------------------------------------------------------------
// K2a: per-(b, f) sum/sumsq over 2048 contiguous floats. One warp per bin.
// ---------------------------------------------------------------------------
__global__ __launch_bounds__(256) void k_fsums(const float* __restrict__ x) {
    int idx = blockIdx.x * 8 + (threadIdx.x >> 5);
    if (idx >= BATCH * FTOT) return;
    int b = idx / FTOT, f = idx - b * FTOT;
    int lane = threadIdx.x & 31;
    float sum = 0.f, sq = 0.f;
#pragma unroll
    for (int ci = 0; ci < 2; ci++) {
        const float4* p =
            (const float4*)(x + ((size_t)(b * 2 + ci) * FTOT + f) * (size_t)(T * 2));
#pragma unroll
        for (int i = 0; i < 8; i++) {
            float4 v = p[lane + i * 32];
            sum += v.x + v.y + v.z + v.w;
            sq += v.x * v.x + v.y * v.y + v.z * v.z + v.w * v.w;
        }
    }
#pragma unroll
    for (int d = 16; d > 0; d >>= 1) {
        sum += __shfl_down_sync(0xffffffffu, sum, d);
        sq += __shfl_down_sync(0xffffffffu, sq, d);
    }
    if (lane == 0) { g_fsum[idx] = sum; g_fsq[idx] = sq; }
}

// K2b: per-(band, batch) reduce bin sums -> mu, rstd
__global__ __launch_bounds__(128) void k_stats2() {
    int band = blockIdx.x, b = blockIdx.y;
    int s = c_start[band], w = c_width[band];
    float sum = 0.f, sq = 0.f;
    for (int j = threadIdx.x; j < w; j += 128) {
        int idx = b * FTOT + s + j;
        sum += g_fsum[idx];
        sq += g_fsq[idx];
    }
#pragma unroll
    for (int d = 16; d > 0; d >>= 1) {
        sum += __shfl_down_sync(0xffffffffu, sum, d);
        sq += __shfl_down_sync(0xffffffffu, sq, d);
    }
    __shared__ float s1[4], s2[4];
    int lane = threadIdx.x & 31, wid = threadIdx.x >> 5;
    if (lane == 0) { s1[wid] = sum; s2[wid] = sq; }
    __syncthreads();
    if (threadIdx.x == 0) {
        sum = s1[0] + s1[1] + s1[2] + s1[3];
        sq = s2[0] + s2[1] + s2[2] + s2[3];
        float N = (float)(4 * w * T);
        float mu = sum / N;
        float var = sq / N - mu * mu;
        g_mu[b * NBANDS + band] = mu;
        g_rstd[b * NBANDS + band] = rsqrtf(var + 1e-5f);
    }
}

// ---------------------------------------------------------------------------
// K3: per-band GEMM via tf32 mma.sync; 3-stage cp.async pipeline.
// Block tile M=128 N=64 K=16, 8 warps (4x2), warp tile 32x32.
// B enters raw f32; tensor core truncates to tf32 in HW.
// ---------------------------------------------------------------------------
__global__ __launch_bounds__(256) void k_gemm(const float* __restrict__ x,
                                              const float* __restrict__ bias,
                                              float* __restrict__ out) {
    const int band = c_perm[blockIdx.z];
    const int b = blockIdx.y;
    const int t0 = blockIdx.x * 64;
    const int s = c_start[band], w = c_width[band];
    const int off = 4 * s;
    const int ch = 4 * w;
    const float* xb = x + (size_t)b * XBATCH;

    __shared__ float As[3][128][20];     // [m][k], stride 20: conflict-free frags
    __shared__ float Bs[3][8][72][2];    // [k-pair][t][r-parity]: conflict-free frags

    const int tid = threadIdx.x;
    const int lane = tid & 31, warp = tid >> 5;
    const int g = lane >> 2, tg = lane & 3;
    const int mw = (warp >> 1) * 32, nw = (warp & 1) * 32;

    const int am0 = tid >> 2;       // A row (and +64)
    const int ak4 = (tid & 3) * 4;  // A k base (float4)
    const int bt = tid & 63;        // B t
    const int bp0 = tid >> 6;       // B k-pair (and +4)

    const int niter = (ch + 15) >> 4;

    auto issue = [&](int st, int k0) {
#pragma unroll
        for (int j = 0; j < 2; j++) {
            int kb = k0 + ak4;
            bool p = kb < ch;
            const float* src =
                g_Wg + (size_t)(am0 + j * 64) * TOTCH + off + (p ? kb : 0);
            cp16(smaddr(&As[st][am0 + j * 64][ak4]), src, p);
        }
#pragma unroll
        for (int j = 0; j < 2; j++) {
            int p = bp0 + j * 4;
            int kk = k0 + 2 * p;
            bool pr = kk < ch;
            int pi = (off + (pr ? kk : 0)) >> 1;
            const float* src = xb + g_xoff2[pi] + (t0 + bt) * 2;
            cp8(smaddr(&Bs[st][p][bt][0]), src, pr);
        }
    };

    float d[2][4][4];
#pragma unroll
    for (int mt = 0; mt < 2; mt++)
#pragma unroll
        for (int nt = 0; nt < 4; nt++)
#pragma unroll
            for (int j = 0; j < 4; j++) d[mt][nt][j] = 0.f;

    issue(0, 0);
    cp_commit();
    issue(1, 16);
    cp_commit();

    for (int it = 0; it < niter; it++) {
        const int cur = it % 3;
        cp_wait1();
        __syncthreads();
        {
            int nst = it + 2;
            if (nst < niter) issue(nst % 3, nst * 16);
            cp_commit();  // always commit (possibly empty) to keep group accounting
        }

#pragma unroll
        for (int kk = 0; kk < 16; kk += 8) {
            uint32_t a[2][4], bb[4][2];
#pragma unroll
            for (int mt = 0; mt < 2; mt++) {
                int rb = mw + mt * 16;
                a[mt][0] = __float_as_uint(As[cur][rb + g][kk + tg]);
                a[mt][1] = __float_as_uint(As[cur][rb + g + 8][kk + tg]);
                a[mt][2] = __float_as_uint(As[cur][rb + g][kk + tg + 4]);
                a[mt][3] = __float_as_uint(As[cur][rb + g + 8][kk + tg + 4]);
            }
            const int p0 = (kk + tg) >> 1, par = tg & 1;
#pragma unroll
            for (int nt = 0; nt < 4; nt++) {
                int cb = nw + nt * 8 + g;
                bb[nt][0] = __float_as_uint(Bs[cur][p0][cb][par]);
                bb[nt][1] = __float_as_uint(Bs[cur][p0 + 2][cb][par]);
            }
#pragma unroll
            for (int mt = 0; mt < 2; mt++)
#pragma unroll
                for (int nt = 0; nt < 4; nt++)
                    asm volatile(
                        "mma.sync.aligned.m16n8k8.row.col.f32.tf32.tf32.f32 "
                        "{%0,%1,%2,%3}, {%4,%5,%6,%7}, {%8,%9}, {%0,%1,%2,%3};"
                        : "+f"(d[mt][nt][0]), "+f"(d[mt][nt][1]),
                          "+f"(d[mt][nt][2]), "+f"(d[mt][nt][3])
                        : "r"(a[mt][0]), "r"(a[mt][1]), "r"(a[mt][2]), "r"(a[mt][3]),
                          "r"(bb[nt][0]), "r"(bb[nt][1]));
        }
    }

    const float mu = g_mu[b * NBANDS + band];
    const float rstd = g_rstd[b * NBANDS + band];
#pragma unroll
    for (int mt = 0; mt < 2; mt++) {
        int o0 = mw + mt * 16 + g;
        int o1 = o0 + 8;
        float add0 = g_Swb[band * OUTCH + o0] - rstd * mu * g_Swg[band * OUTCH + o0] +
                     bias[band * OUTCH + o0];
        float add1 = g_Swb[band * OUTCH + o1] - rstd * mu * g_Swg[band * OUTCH + o1] +
                     bias[band * OUTCH + o1];
#pragma unroll
        for (int nt = 0; nt < 4; nt++) {
            int t = t0 + nw + nt * 8 + 2 * tg;
            float2 v0 = {rstd * d[mt][nt][0] + add0, rstd * d[mt][nt][1] + add0};
            float2 v1 = {rstd * d[mt][nt][2] + add1, rstd * d[mt][nt][3] + add1};
            *(float2*)(out + (((size_t)(b * OUTCH + o0) * NBANDS + band) * T + t)) = v0;
            *(float2*)(out + (((size_t)(b * OUTCH + o1) * NBANDS + band) * T + t)) = v1;
        }
    }
}

extern "C" void kernel_launch(void* const* d_in, const int* in_sizes, int n_in,
                              void* d_out, int out_size) {
    (void)in_sizes; (void)n_in; (void)out_size;
    const float* x = (const float*)d_in[0];
    const float* gamma = (const float*)d_in[1];
    const float* beta = (const float*)d_in[2];
    const float* W = (const float*)d_in[3];
    const float* bias = (const float*)d_in[4];
    float* out = (float*)d_out;

    k_offs<<<(TOTCH + 255) / 256, 256>>>();
    k_prep<<<dim3(NBANDS, OUTCH), 256>>>(W, gamma);
    k_wsums<<<dim3(NBANDS, OUTCH), 128>>>(W, gamma, beta);
    k_fsums<<<(BATCH * FTOT + 7) / 8, 256>>>(x);
    k_stats2<<<dim3(NBANDS, BATCH), 128>>>();
    k_gemm<<<dim3(T / 64, BATCH, NBANDS), 256>>>(x, bias, out);
}